// round 7
// baseline (speedup 1.0000x reference)
#include <cuda_runtime.h>
#include <cstdint>
#include <utility>

// ============================================================================
// Compile-time structure builder. Reproduces the reference enumeration exactly
// (to recover each term's original index into CG_vals), then re-sorts terms:
//   major: m_total = m1+m2  (7 groups, -3..3)
//   mid:   (M1, M2) pair    (pair products factorized)
//   minor: l (output degree) -> accumulator slot l - |m|
// The CG*weight table lives in GLOBAL memory (built once by a tiny setup
// kernel), pair-interleaved per channel-group: slot s, channel-pair cp at ull
// index (s/2)*16 + cp*2 + (s&1). One LDG.128 per cp feeds 2 terms; the 30.6KB
// per-cgroup slice is L1-resident in the hot kernel.
// ============================================================================
namespace wtp {

constexpr int LMAX = 3;
constexpr int MOUT = 16;
constexpr int NNZ  = 478;
constexpr int C    = 128;
constexpr int NCHP = 8;          // channel-pairs per block (16 channels)
constexpr int NSLOT = 16;        // row slots per block
constexpr int RPT  = 2;          // rows per thread
constexpr int NROWB = NSLOT * RPT;       // 32 rows per block
constexpr int NTHREADS = NCHP * NSLOT;   // 128
constexpr int NGRP = 7;
constexpr int NCGRP = C / (2 * NCHP);    // 8 channel groups
constexpr int SLICE = ((NNZ + 1) / 2) * 2 * NCHP;  // 3824 ull per cgroup

struct Structure {
    int m1[NNZ];
    int m2[NNZ];
    int aidx[NNZ];
    int orig[NNZ];
    bool newpair[NNZ];
    int start[NGRP + 1];
    int count;
};

constexpr Structure build_structure() {
    Structure s{};
    int tl[64] = {}, tl1[64] = {}, tl2[64] = {};
    int nt = 0;
    for (int l1 = 0; l1 <= LMAX; l1++)
        for (int l2 = 0; l2 <= LMAX; l2++) {
            int lo = (l1 > l2) ? (l1 - l2) : (l2 - l1);
            int hi = (l1 + l2 < LMAX) ? (l1 + l2) : LMAX;
            for (int l = lo; l <= hi; l++) { tl[nt]=l; tl1[nt]=l1; tl2[nt]=l2; nt++; }
        }
    int rm1[NNZ]={}, rm2[NNZ]={}, rl[NNZ]={}, rm[NNZ]={};
    int cnt = 0;
    for (int l = 0; l <= LMAX; l++)
        for (int m = -l; m <= l; m++) {
            for (int t = 0; t < nt; t++) {
                if (tl[t] != l) continue;
                int l1 = tl1[t], l2 = tl2[t];
                int lo = (-l1 > m - l2) ? -l1 : (m - l2);
                int hi = (l1 < m + l2) ? l1 : (m + l2);
                for (int m1 = lo; m1 <= hi; m1++) {
                    int m2 = m - m1;
                    rm1[cnt] = l1*l1 + l1 + m1;
                    rm2[cnt] = l2*l2 + l2 + m2;
                    rl[cnt]  = l;
                    rm[cnt]  = m;
                    cnt++;
                }
            }
        }
    s.count = cnt;
    int key[NNZ] = {};
    for (int i = 0; i < cnt; i++)
        key[i] = (((rm[i] + 3) * 16 + rm1[i]) * 16 + rm2[i]) * 4 + rl[i];
    int sm[NNZ] = {};
    for (int i = 0; i < cnt; i++) {
        int rank = 0;
        for (int j = 0; j < cnt; j++)
            if (key[j] < key[i] || (key[j] == key[i] && j < i)) rank++;
        int am = rm[i] < 0 ? -rm[i] : rm[i];
        s.m1[rank]   = rm1[i];
        s.m2[rank]   = rm2[i];
        s.aidx[rank] = rl[i] - am;
        s.orig[rank] = i;
        sm[rank]     = rm[i];
    }
    for (int i = 0; i < cnt; i++)
        s.newpair[i] = (i == 0) || (s.m1[i] != s.m1[i-1]) || (s.m2[i] != s.m2[i-1]);
    for (int g = 0; g <= NGRP; g++) {
        int st = cnt;
        for (int i = 0; i < cnt; i++)
            if (sm[i] + 3 >= g) { st = i; break; }
        s.start[g] = st;
    }
    return s;
}

constexpr Structure S = build_structure();
static_assert(S.count == NNZ, "term count mismatch vs reference structure");
static_assert(S.start[0] == 0 && S.start[NGRP] == NNZ, "group partition broken");

// sorted slot for each reference index (runtime-indexed -> constant memory)
struct Inv { int slot[NNZ]; };
constexpr Inv build_inv() {
    Inv v{};
    for (int t = 0; t < NNZ; t++) v.slot[S.orig[t]] = t;
    return v;
}
__constant__ Inv INV_c = build_inv();

// ull index of (sorted slot s, channel pair cp) within a cgroup slice
__host__ __device__ constexpr int cgw_idx(int s, int cp) {
    return (s >> 1) * (2 * NCHP) + cp * 2 + (s & 1);
}

} // namespace wtp

using ull = unsigned long long;

// Precomputed CG*weight table, pair-interleaved, one slice per channel group.
__device__ ull cgw_g[wtp::NCGRP][wtp::SLICE];

// ============================================================================
// Setup kernel: builds the full table ONCE (478 terms x 64 channel-pairs).
// ============================================================================
__global__ void __launch_bounds__(256)
wtp_build_kernel(const float* __restrict__ w,
                 const float* __restrict__ cg,
                 const int*   __restrict__ l_ind)
{
    const int total = wtp::NNZ * (wtp::C / 2);  // 30592 float2 entries
    for (int i = blockIdx.x * blockDim.x + threadIdx.x; i < total;
         i += gridDim.x * blockDim.x) {
        const int t   = i >> 6;          // term, reference order
        const int cpr = i & 63;          // global channel pair 0..63
        const int g   = cpr >> 3;        // channel group
        const int cp  = cpr & 7;         // pair within group
        const float cgv = __ldg(cg + t);
        const int   li  = __ldg(l_ind + t);
        const float2 wv =
            *reinterpret_cast<const float2*>(w + li * wtp::C + cpr * 2);
        reinterpret_cast<float2*>(&cgw_g[g][wtp::cgw_idx(wtp::INV_c.slot[t], cp)])[0] =
            make_float2(cgv * wv.x, cgv * wv.y);
    }
}

// ============================================================================
// Per-term executor with preloaded wv. Packed f32x2, 2 rows per thread.
// ============================================================================
template <int T>
__device__ __forceinline__ void do_term_wv(
    const ull wv,
    const ull (&X1)[wtp::RPT][wtp::MOUT],
    const ull (&X2)[wtp::RPT][wtp::MOUT],
    ull (&ACC)[wtp::RPT][4],
    ull (&p)[wtp::RPT])
{
    constexpr int m1 = wtp::S.m1[T];
    constexpr int m2 = wtp::S.m2[T];
    constexpr int ai = wtp::S.aidx[T];
    if constexpr (wtp::S.newpair[T]) {
        asm("mul.rn.f32x2 %0, %1, %2;" : "=l"(p[0]) : "l"(X1[0][m1]), "l"(X2[0][m2]));
        asm("mul.rn.f32x2 %0, %1, %2;" : "=l"(p[1]) : "l"(X1[1][m1]), "l"(X2[1][m2]));
    }
    asm("fma.rn.f32x2 %0, %1, %2, %3;" : "=l"(ACC[0][ai]) : "l"(p[0]), "l"(wv), "l"(ACC[0][ai]));
    asm("fma.rn.f32x2 %0, %1, %2, %3;" : "=l"(ACC[1][ai]) : "l"(p[1]), "l"(wv), "l"(ACC[1][ai]));
}

// One LDG.128 (L1-hit) feeds two consecutive sorted terms (slots 2P, 2P+1).
template <int PB, int... Is>
__device__ __forceinline__ void run_pairs(
    std::integer_sequence<int, Is...>,
    const ull* __restrict__ cgw_cp,   // = slice + cp*2
    const ull (&X1)[wtp::RPT][wtp::MOUT],
    const ull (&X2)[wtp::RPT][wtp::MOUT],
    ull (&ACC)[wtp::RPT][4],
    ull (&p)[wtp::RPT])
{
    (([&] {
        constexpr int P = PB + Is;
        const ulonglong2 wv2 =
            __ldg(reinterpret_cast<const ulonglong2*>(cgw_cp + P * 16));
        do_term_wv<2 * P>(wv2.x, X1, X2, ACC, p);
        do_term_wv<2 * P + 1>(wv2.y, X1, X2, ACC, p);
    }()), ...);
}

template <int G>
__device__ __forceinline__ void run_group(
    const ull* __restrict__ cgw_cp,
    const ull (&X1)[wtp::RPT][wtp::MOUT],
    const ull (&X2)[wtp::RPT][wtp::MOUT],
    ull* __restrict__ op0,
    ull* __restrict__ op1)
{
    constexpr int m  = G - 3;
    constexpr int la = m < 0 ? -m : m;
    constexpr int ns = 4 - la;
    constexpr int nb = wtp::S.start[G];
    constexpr int ne = wtp::S.start[G + 1];
    constexpr int first = (nb & 1) ? nb + 1 : nb;
    constexpr int npair = (ne - first) / 2;
    constexpr int tail  = first + 2 * npair;

    ull ACC[wtp::RPT][4] = {};
    ull p[wtp::RPT] = {};

    if constexpr (nb & 1)
        do_term_wv<nb>(__ldg(cgw_cp + (nb >> 1) * 16 + 1), X1, X2, ACC, p);
    run_pairs<first / 2>(std::make_integer_sequence<int, npair>{},
                         cgw_cp, X1, X2, ACC, p);
    if constexpr (tail < ne)
        do_term_wv<tail>(__ldg(cgw_cp + (tail >> 1) * 16), X1, X2, ACC, p);

    #pragma unroll
    for (int i = 0; i < ns; i++) {
        constexpr int CC = wtp::C / 2;
        const int l = la + i;
        op0[(l * l + l + m) * CC] = ACC[0][i];
        op1[(l * l + l + m) * CC] = ACC[1][i];
    }
}

// ============================================================================
// Hot kernel. Block = 128 threads = 8 ch-pairs x 16 row-slots; each thread
// owns 2 rows -> 16 channels x 32 rows per block. Grid = 512. NO smem, no
// barrier, no per-block build: wv comes straight from the precomputed global
// table (L1-resident, 30.6 KB per cgroup).
// ============================================================================
__global__ void __launch_bounds__(wtp::NTHREADS, 3)
wtp_kernel(const float* __restrict__ x1,
           const float* __restrict__ x2,
           float* __restrict__ out)
{
    const int tid     = threadIdx.x;
    const int cgroup  = blockIdx.x & 7;
    const int rowbase = (blockIdx.x >> 3) * wtp::NROWB;
    const int cp      = tid & (wtp::NCHP - 1);
    const int rs      = tid >> 3;
    const int cbase   = cgroup * 16;

    const int row0 = rowbase + rs;
    const int row1 = row0 + wtp::NSLOT;
    const size_t base0 = (size_t)row0 * wtp::MOUT * wtp::C + cbase + cp * 2;
    const size_t base1 = (size_t)row1 * wtp::MOUT * wtp::C + cbase + cp * 2;
    const ull* x1p0 = reinterpret_cast<const ull*>(x1 + base0);
    const ull* x2p0 = reinterpret_cast<const ull*>(x2 + base0);
    const ull* x1p1 = reinterpret_cast<const ull*>(x1 + base1);
    const ull* x2p1 = reinterpret_cast<const ull*>(x2 + base1);
    ull* op0 = reinterpret_cast<ull*>(out + base0);
    ull* op1 = reinterpret_cast<ull*>(out + base1);

    ull X1[wtp::RPT][wtp::MOUT], X2[wtp::RPT][wtp::MOUT];
    #pragma unroll
    for (int m = 0; m < wtp::MOUT; m++) {
        constexpr int CC = wtp::C / 2;
        X1[0][m] = x1p0[m * CC];
        X2[0][m] = x2p0[m * CC];
        X1[1][m] = x1p1[m * CC];
        X2[1][m] = x2p1[m * CC];
    }

    const ull* cgw_cp = cgw_g[cgroup] + cp * 2;
    run_group<0>(cgw_cp, X1, X2, op0, op1);
    run_group<1>(cgw_cp, X1, X2, op0, op1);
    run_group<2>(cgw_cp, X1, X2, op0, op1);
    run_group<3>(cgw_cp, X1, X2, op0, op1);
    run_group<4>(cgw_cp, X1, X2, op0, op1);
    run_group<5>(cgw_cp, X1, X2, op0, op1);
    run_group<6>(cgw_cp, X1, X2, op0, op1);
}

// ============================================================================
// Launch. Inputs (metadata order): x1, x2, weight, CG_vals, M1, M2, l_ind, M_seg
// ============================================================================
extern "C" void kernel_launch(void* const* d_in, const int* in_sizes, int n_in,
                              void* d_out, int out_size)
{
    const float* x1    = (const float*)d_in[0];
    const float* x2    = (const float*)d_in[1];
    const float* w     = (const float*)d_in[2];
    const float* cg    = (const float*)d_in[3];
    const int*   l_ind = (const int*)d_in[6];
    float*       out   = (float*)d_out;

    const int B = in_sizes[0] / (wtp::MOUT * wtp::C);   // 2048

    // 1) build CG*weight table once (30592 float2 entries)
    wtp_build_kernel<<<120, 256>>>(w, cg, l_ind);

    // 2) hot kernel
    const int grid = (B / wtp::NROWB) * wtp::NCGRP;     // 64 * 8 = 512
    wtp_kernel<<<grid, wtp::NTHREADS>>>(x1, x2, out);
}

// round 8
// speedup vs baseline: 2.3303x; 2.3303x over previous
#include <cuda_runtime.h>
#include <cstdint>
#include <utility>

// ============================================================================
// Compile-time structure builder. Reproduces the reference enumeration exactly,
// then re-sorts terms:
//   major: m_total = m1+m2  (7 groups, -3..3)
//   mid:   (M1, M2) pair    (pair products factorized)
//   minor: l (output degree) -> accumulator slot l - |m|
// The CG*weight table is built ONCE by a setup kernel into global memory in
// [term_reference_order][channel_pair] layout per channel group; each hot block
// bulk-copies its 30.6 KB slice into shared memory (no gathers, no dependent
// loads) and runs the R3-proven LDS.64 hot loop.
// ============================================================================
namespace wtp {

constexpr int LMAX = 3;
constexpr int MOUT = 16;
constexpr int NNZ  = 478;
constexpr int C    = 128;
constexpr int NCHP = 8;          // channel-pairs per block (16 channels)
constexpr int NSLOT = 16;        // row slots per block
constexpr int RPT  = 2;          // rows per thread
constexpr int NROWB = NSLOT * RPT;       // 32 rows per block
constexpr int NTHREADS = NCHP * NSLOT;   // 128
constexpr int NGRP = 7;
constexpr int NCGRP = C / (2 * NCHP);    // 8 channel groups
constexpr int SLICE = NNZ * NCHP;        // 3824 ull per cgroup slice

struct Structure {
    int m1[NNZ];
    int m2[NNZ];
    int aidx[NNZ];
    int orig[NNZ];
    bool newpair[NNZ];
    int start[NGRP + 1];
    int count;
};

constexpr Structure build_structure() {
    Structure s{};
    int tl[64] = {}, tl1[64] = {}, tl2[64] = {};
    int nt = 0;
    for (int l1 = 0; l1 <= LMAX; l1++)
        for (int l2 = 0; l2 <= LMAX; l2++) {
            int lo = (l1 > l2) ? (l1 - l2) : (l2 - l1);
            int hi = (l1 + l2 < LMAX) ? (l1 + l2) : LMAX;
            for (int l = lo; l <= hi; l++) { tl[nt]=l; tl1[nt]=l1; tl2[nt]=l2; nt++; }
        }
    int rm1[NNZ]={}, rm2[NNZ]={}, rl[NNZ]={}, rm[NNZ]={};
    int cnt = 0;
    for (int l = 0; l <= LMAX; l++)
        for (int m = -l; m <= l; m++) {
            for (int t = 0; t < nt; t++) {
                if (tl[t] != l) continue;
                int l1 = tl1[t], l2 = tl2[t];
                int lo = (-l1 > m - l2) ? -l1 : (m - l2);
                int hi = (l1 < m + l2) ? l1 : (m + l2);
                for (int m1 = lo; m1 <= hi; m1++) {
                    int m2 = m - m1;
                    rm1[cnt] = l1*l1 + l1 + m1;
                    rm2[cnt] = l2*l2 + l2 + m2;
                    rl[cnt]  = l;
                    rm[cnt]  = m;
                    cnt++;
                }
            }
        }
    s.count = cnt;
    int key[NNZ] = {};
    for (int i = 0; i < cnt; i++)
        key[i] = (((rm[i] + 3) * 16 + rm1[i]) * 16 + rm2[i]) * 4 + rl[i];
    int sm[NNZ] = {};
    for (int i = 0; i < cnt; i++) {
        int rank = 0;
        for (int j = 0; j < cnt; j++)
            if (key[j] < key[i] || (key[j] == key[i] && j < i)) rank++;
        int am = rm[i] < 0 ? -rm[i] : rm[i];
        s.m1[rank]   = rm1[i];
        s.m2[rank]   = rm2[i];
        s.aidx[rank] = rl[i] - am;
        s.orig[rank] = i;
        sm[rank]     = rm[i];
    }
    for (int i = 0; i < cnt; i++)
        s.newpair[i] = (i == 0) || (s.m1[i] != s.m1[i-1]) || (s.m2[i] != s.m2[i-1]);
    for (int g = 0; g <= NGRP; g++) {
        int st = cnt;
        for (int i = 0; i < cnt; i++)
            if (sm[i] + 3 >= g) { st = i; break; }
        s.start[g] = st;
    }
    return s;
}

constexpr Structure S = build_structure();
static_assert(S.count == NNZ, "term count mismatch vs reference structure");
static_assert(S.start[0] == 0 && S.start[NGRP] == NNZ, "group partition broken");

} // namespace wtp

using ull = unsigned long long;

// Precomputed CG*weight table: per cgroup, [term_reference_order][cp].
__device__ ull cgw_g[wtp::NCGRP][wtp::SLICE];

// ============================================================================
// Setup kernel: builds the full table ONCE (478 terms x 64 channel-pairs).
// ============================================================================
__global__ void __launch_bounds__(256)
wtp_build_kernel(const float* __restrict__ w,
                 const float* __restrict__ cg,
                 const int*   __restrict__ l_ind)
{
    const int total = wtp::NNZ * (wtp::C / 2);  // 30592 float2 entries
    for (int i = blockIdx.x * blockDim.x + threadIdx.x; i < total;
         i += gridDim.x * blockDim.x) {
        const int t   = i >> 6;          // term, reference order
        const int cpr = i & 63;          // global channel pair 0..63
        const int g   = cpr >> 3;        // channel group
        const int cp  = cpr & 7;         // pair within group
        const float cgv = __ldg(cg + t);
        const int   li  = __ldg(l_ind + t);
        const float2 wv =
            *reinterpret_cast<const float2*>(w + li * wtp::C + cpr * 2);
        reinterpret_cast<float2*>(&cgw_g[g][t * wtp::NCHP + cp])[0] =
            make_float2(cgv * wv.x, cgv * wv.y);
    }
}

// ============================================================================
// Per-term executor (R3-proven): one LDS.64 per term, compile-time indices,
// packed f32x2 math, 2 rows per thread sharing the wv register.
// ============================================================================
template <int T>
__device__ __forceinline__ void do_term(
    const ull* __restrict__ cgw_tp,   // = smem + cp
    const ull (&X1)[wtp::RPT][wtp::MOUT],
    const ull (&X2)[wtp::RPT][wtp::MOUT],
    ull (&ACC)[wtp::RPT][4],
    ull (&p)[wtp::RPT])
{
    constexpr int m1 = wtp::S.m1[T];
    constexpr int m2 = wtp::S.m2[T];
    constexpr int ai = wtp::S.aidx[T];
    constexpr int og = wtp::S.orig[T];
    if constexpr (wtp::S.newpair[T]) {
        asm("mul.rn.f32x2 %0, %1, %2;" : "=l"(p[0]) : "l"(X1[0][m1]), "l"(X2[0][m2]));
        asm("mul.rn.f32x2 %0, %1, %2;" : "=l"(p[1]) : "l"(X1[1][m1]), "l"(X2[1][m2]));
    }
    const ull wv = cgw_tp[og * wtp::NCHP];
    asm("fma.rn.f32x2 %0, %1, %2, %3;" : "=l"(ACC[0][ai]) : "l"(p[0]), "l"(wv), "l"(ACC[0][ai]));
    asm("fma.rn.f32x2 %0, %1, %2, %3;" : "=l"(ACC[1][ai]) : "l"(p[1]), "l"(wv), "l"(ACC[1][ai]));
}

template <int Base, int... Is>
__device__ __forceinline__ void run_range(
    std::integer_sequence<int, Is...>,
    const ull* __restrict__ cgw_tp,
    const ull (&X1)[wtp::RPT][wtp::MOUT],
    const ull (&X2)[wtp::RPT][wtp::MOUT],
    ull (&ACC)[wtp::RPT][4],
    ull (&p)[wtp::RPT])
{
    ((do_term<Base + Is>(cgw_tp, X1, X2, ACC, p)), ...);
}

template <int G>
__device__ __forceinline__ void run_group(
    const ull* __restrict__ cgw_tp,
    const ull (&X1)[wtp::RPT][wtp::MOUT],
    const ull (&X2)[wtp::RPT][wtp::MOUT],
    ull* __restrict__ op0,
    ull* __restrict__ op1)
{
    constexpr int m  = G - 3;
    constexpr int la = m < 0 ? -m : m;
    constexpr int ns = 4 - la;
    constexpr int nb = wtp::S.start[G];
    constexpr int ne = wtp::S.start[G + 1];

    ull ACC[wtp::RPT][4] = {};
    ull p[wtp::RPT] = {};
    run_range<nb>(std::make_integer_sequence<int, ne - nb>{}, cgw_tp, X1, X2, ACC, p);

    #pragma unroll
    for (int i = 0; i < ns; i++) {
        constexpr int CC = wtp::C / 2;
        const int l = la + i;
        op0[(l * l + l + m) * CC] = ACC[0][i];
        op1[(l * l + l + m) * CC] = ACC[1][i];
    }
}

// ============================================================================
// Hot kernel. Block = 128 threads = 8 ch-pairs x 16 row-slots; each thread
// owns 2 rows -> 16 channels x 32 rows per block. Grid = 512. The smem cgw
// table is a BULK COPY of the precomputed global slice (coalesced 16B chunks,
// no dependent loads) instead of a per-block rebuild.
// ============================================================================
__global__ void __launch_bounds__(wtp::NTHREADS, 3)
wtp_kernel(const float* __restrict__ x1,
           const float* __restrict__ x2,
           float* __restrict__ out)
{
    extern __shared__ ull cgw_s[];  // [NNZ][NCHP], reference term order

    const int tid     = threadIdx.x;
    const int cgroup  = blockIdx.x & 7;
    const int rowbase = (blockIdx.x >> 3) * wtp::NROWB;
    const int cp      = tid & (wtp::NCHP - 1);
    const int rs      = tid >> 3;
    const int cbase   = cgroup * 16;

    // --- bulk copy global slice -> smem (1912 x 16B, fully coalesced) ---
    {
        const ulonglong2* src = reinterpret_cast<const ulonglong2*>(cgw_g[cgroup]);
        ulonglong2*       dst = reinterpret_cast<ulonglong2*>(cgw_s);
        #pragma unroll
        for (int i = tid; i < wtp::SLICE / 2; i += wtp::NTHREADS)
            dst[i] = src[i];
    }
    __syncthreads();

    const int row0 = rowbase + rs;
    const int row1 = row0 + wtp::NSLOT;
    const size_t base0 = (size_t)row0 * wtp::MOUT * wtp::C + cbase + cp * 2;
    const size_t base1 = (size_t)row1 * wtp::MOUT * wtp::C + cbase + cp * 2;
    const ull* x1p0 = reinterpret_cast<const ull*>(x1 + base0);
    const ull* x2p0 = reinterpret_cast<const ull*>(x2 + base0);
    const ull* x1p1 = reinterpret_cast<const ull*>(x1 + base1);
    const ull* x2p1 = reinterpret_cast<const ull*>(x2 + base1);
    ull* op0 = reinterpret_cast<ull*>(out + base0);
    ull* op1 = reinterpret_cast<ull*>(out + base1);

    ull X1[wtp::RPT][wtp::MOUT], X2[wtp::RPT][wtp::MOUT];
    #pragma unroll
    for (int m = 0; m < wtp::MOUT; m++) {
        constexpr int CC = wtp::C / 2;
        X1[0][m] = x1p0[m * CC];
        X2[0][m] = x2p0[m * CC];
        X1[1][m] = x1p1[m * CC];
        X2[1][m] = x2p1[m * CC];
    }

    const ull* cgw_tp = cgw_s + cp;
    run_group<0>(cgw_tp, X1, X2, op0, op1);
    run_group<1>(cgw_tp, X1, X2, op0, op1);
    run_group<2>(cgw_tp, X1, X2, op0, op1);
    run_group<3>(cgw_tp, X1, X2, op0, op1);
    run_group<4>(cgw_tp, X1, X2, op0, op1);
    run_group<5>(cgw_tp, X1, X2, op0, op1);
    run_group<6>(cgw_tp, X1, X2, op0, op1);
}

// ============================================================================
// Launch. Inputs (metadata order): x1, x2, weight, CG_vals, M1, M2, l_ind, M_seg
// ============================================================================
extern "C" void kernel_launch(void* const* d_in, const int* in_sizes, int n_in,
                              void* d_out, int out_size)
{
    const float* x1    = (const float*)d_in[0];
    const float* x2    = (const float*)d_in[1];
    const float* w     = (const float*)d_in[2];
    const float* cg    = (const float*)d_in[3];
    const int*   l_ind = (const int*)d_in[6];
    float*       out   = (float*)d_out;

    const int B = in_sizes[0] / (wtp::MOUT * wtp::C);   // 2048
    const int smem = wtp::SLICE * 8;                    // 30592 bytes

    cudaFuncSetAttribute(wtp_kernel, cudaFuncAttributeMaxDynamicSharedMemorySize, smem);

    // 1) build CG*weight table once
    wtp_build_kernel<<<120, 256>>>(w, cg, l_ind);

    // 2) hot kernel
    const int grid = (B / wtp::NROWB) * wtp::NCGRP;     // 64 * 8 = 512
    wtp_kernel<<<grid, wtp::NTHREADS, smem>>>(x1, x2, out);
}

// round 10
// speedup vs baseline: 2.6142x; 1.1218x over previous
#include <cuda_runtime.h>
#include <cstdint>
#include <utility>

// ============================================================================
// Compile-time structure builder. Reproduces the reference enumeration exactly,
// then re-sorts terms:
//   major: m_total = m1+m2  (7 groups, -3..3)
//   mid:   (M1, M2) pair    (pair products factorized)
//   minor: l (output degree) -> accumulator slot l - |m|
// CG*weight table built ONCE by a setup kernel into global memory
// ([term_ref][cp] per cgroup); hot blocks bulk-copy their 30.6KB slice to smem
// and run a SOFTWARE-PIPELINED LDS.64 hot loop (depth-8 register ring covers
// the 29-cyc shared-memory latency inside a single warp).
// ============================================================================
namespace wtp {

constexpr int LMAX = 3;
constexpr int MOUT = 16;
constexpr int NNZ  = 478;
constexpr int C    = 128;
constexpr int NCHP = 8;          // channel-pairs per block (16 channels)
constexpr int NSLOT = 16;        // row slots per block
constexpr int RPT  = 2;          // rows per thread
constexpr int NROWB = NSLOT * RPT;       // 32 rows per block
constexpr int NTHREADS = NCHP * NSLOT;   // 128
constexpr int NGRP = 7;
constexpr int NCGRP = C / (2 * NCHP);    // 8 channel groups
constexpr int SLICE = NNZ * NCHP;        // 3824 ull per cgroup slice
constexpr int PIPE = 8;          // wv prefetch depth (register ring)

struct Structure {
    int m1[NNZ];
    int m2[NNZ];
    int aidx[NNZ];
    int orig[NNZ];
    bool newpair[NNZ];
    int start[NGRP + 1];
    int count;
};

constexpr Structure build_structure() {
    Structure s{};
    int tl[64] = {}, tl1[64] = {}, tl2[64] = {};
    int nt = 0;
    for (int l1 = 0; l1 <= LMAX; l1++)
        for (int l2 = 0; l2 <= LMAX; l2++) {
            int lo = (l1 > l2) ? (l1 - l2) : (l2 - l1);
            int hi = (l1 + l2 < LMAX) ? (l1 + l2) : LMAX;
            for (int l = lo; l <= hi; l++) { tl[nt]=l; tl1[nt]=l1; tl2[nt]=l2; nt++; }
        }
    int rm1[NNZ]={}, rm2[NNZ]={}, rl[NNZ]={}, rm[NNZ]={};
    int cnt = 0;
    for (int l = 0; l <= LMAX; l++)
        for (int m = -l; m <= l; m++) {
            for (int t = 0; t < nt; t++) {
                if (tl[t] != l) continue;
                int l1 = tl1[t], l2 = tl2[t];
                int lo = (-l1 > m - l2) ? -l1 : (m - l2);
                int hi = (l1 < m + l2) ? l1 : (m + l2);
                for (int m1 = lo; m1 <= hi; m1++) {
                    int m2 = m - m1;
                    rm1[cnt] = l1*l1 + l1 + m1;
                    rm2[cnt] = l2*l2 + l2 + m2;
                    rl[cnt]  = l;
                    rm[cnt]  = m;
                    cnt++;
                }
            }
        }
    s.count = cnt;
    int key[NNZ] = {};
    for (int i = 0; i < cnt; i++)
        key[i] = (((rm[i] + 3) * 16 + rm1[i]) * 16 + rm2[i]) * 4 + rl[i];
    int sm[NNZ] = {};
    for (int i = 0; i < cnt; i++) {
        int rank = 0;
        for (int j = 0; j < cnt; j++)
            if (key[j] < key[i] || (key[j] == key[i] && j < i)) rank++;
        int am = rm[i] < 0 ? -rm[i] : rm[i];
        s.m1[rank]   = rm1[i];
        s.m2[rank]   = rm2[i];
        s.aidx[rank] = rl[i] - am;
        s.orig[rank] = i;
        sm[rank]     = rm[i];
    }
    for (int i = 0; i < cnt; i++)
        s.newpair[i] = (i == 0) || (s.m1[i] != s.m1[i-1]) || (s.m2[i] != s.m2[i-1]);
    for (int g = 0; g <= NGRP; g++) {
        int st = cnt;
        for (int i = 0; i < cnt; i++)
            if (sm[i] + 3 >= g) { st = i; break; }
        s.start[g] = st;
    }
    return s;
}

constexpr Structure S = build_structure();
static_assert(S.count == NNZ, "term count mismatch vs reference structure");
static_assert(S.start[0] == 0 && S.start[NGRP] == NNZ, "group partition broken");

} // namespace wtp

using ull = unsigned long long;

// Precomputed CG*weight table: per cgroup, [term_reference_order][cp].
__device__ ull cgw_g[wtp::NCGRP][wtp::SLICE];

// ============================================================================
// Setup kernel: builds the full table ONCE (478 terms x 64 channel-pairs).
// ============================================================================
__global__ void __launch_bounds__(256)
wtp_build_kernel(const float* __restrict__ w,
                 const float* __restrict__ cg,
                 const int*   __restrict__ l_ind)
{
    const int total = wtp::NNZ * (wtp::C / 2);  // 30592 float2 entries
    for (int i = blockIdx.x * blockDim.x + threadIdx.x; i < total;
         i += gridDim.x * blockDim.x) {
        const int t   = i >> 6;          // term, reference order
        const int cpr = i & 63;          // global channel pair 0..63
        const int g   = cpr >> 3;        // channel group
        const int cp  = cpr & 7;         // pair within group
        const float cgv = __ldg(cg + t);
        const int   li  = __ldg(l_ind + t);
        const float2 wv =
            *reinterpret_cast<const float2*>(w + li * wtp::C + cpr * 2);
        reinterpret_cast<float2*>(&cgw_g[g][t * wtp::NCHP + cp])[0] =
            make_float2(cgv * wv.x, cgv * wv.y);
    }
}

// ============================================================================
// Per-term executor with a depth-PIPE software pipeline: consume wbuf[T%PIPE]
// (loaded PIPE terms ago), refill the slot with term T+PIPE's wv.
// All structure accesses bound to constexpr locals first (device-code rule).
// ============================================================================
template <int T>
__device__ __forceinline__ void do_term(
    const ull* __restrict__ cgw_tp,   // = smem + cp
    ull (&wbuf)[wtp::PIPE],
    const ull (&X1)[wtp::RPT][wtp::MOUT],
    const ull (&X2)[wtp::RPT][wtp::MOUT],
    ull (&ACC)[wtp::RPT][4],
    ull (&p)[wtp::RPT])
{
    constexpr int m1 = wtp::S.m1[T];
    constexpr int m2 = wtp::S.m2[T];
    constexpr int ai = wtp::S.aidx[T];
    constexpr bool np = wtp::S.newpair[T];

    const ull wv = wbuf[T % wtp::PIPE];
    if constexpr (T + wtp::PIPE < wtp::NNZ) {
        constexpr int og_next = wtp::S.orig[T + wtp::PIPE];
        wbuf[T % wtp::PIPE] = cgw_tp[og_next * wtp::NCHP];
    }
    if constexpr (np) {
        asm("mul.rn.f32x2 %0, %1, %2;" : "=l"(p[0]) : "l"(X1[0][m1]), "l"(X2[0][m2]));
        asm("mul.rn.f32x2 %0, %1, %2;" : "=l"(p[1]) : "l"(X1[1][m1]), "l"(X2[1][m2]));
    }
    asm("fma.rn.f32x2 %0, %1, %2, %3;" : "=l"(ACC[0][ai]) : "l"(p[0]), "l"(wv), "l"(ACC[0][ai]));
    asm("fma.rn.f32x2 %0, %1, %2, %3;" : "=l"(ACC[1][ai]) : "l"(p[1]), "l"(wv), "l"(ACC[1][ai]));
}

// Preload one ring slot; binds S.orig[I] to a constexpr BEFORE device use.
template <int I>
__device__ __forceinline__ void pipe_preload_one(
    const ull* __restrict__ cgw_tp,
    ull (&wbuf)[wtp::PIPE])
{
    constexpr int og = wtp::S.orig[I];
    wbuf[I] = cgw_tp[og * wtp::NCHP];
}

template <int... Is>
__device__ __forceinline__ void pipe_prologue(
    std::integer_sequence<int, Is...>,
    const ull* __restrict__ cgw_tp,
    ull (&wbuf)[wtp::PIPE])
{
    ((pipe_preload_one<Is>(cgw_tp, wbuf)), ...);
}

template <int Base, int... Is>
__device__ __forceinline__ void run_range(
    std::integer_sequence<int, Is...>,
    const ull* __restrict__ cgw_tp,
    ull (&wbuf)[wtp::PIPE],
    const ull (&X1)[wtp::RPT][wtp::MOUT],
    const ull (&X2)[wtp::RPT][wtp::MOUT],
    ull (&ACC)[wtp::RPT][4],
    ull (&p)[wtp::RPT])
{
    ((do_term<Base + Is>(cgw_tp, wbuf, X1, X2, ACC, p)), ...);
}

template <int G>
__device__ __forceinline__ void run_group(
    const ull* __restrict__ cgw_tp,
    ull (&wbuf)[wtp::PIPE],
    const ull (&X1)[wtp::RPT][wtp::MOUT],
    const ull (&X2)[wtp::RPT][wtp::MOUT],
    ull* __restrict__ op0,
    ull* __restrict__ op1)
{
    constexpr int m  = G - 3;
    constexpr int la = m < 0 ? -m : m;
    constexpr int ns = 4 - la;
    constexpr int nb = wtp::S.start[G];
    constexpr int ne = wtp::S.start[G + 1];

    ull ACC[wtp::RPT][4] = {};
    ull p[wtp::RPT] = {};
    run_range<nb>(std::make_integer_sequence<int, ne - nb>{},
                  cgw_tp, wbuf, X1, X2, ACC, p);

    #pragma unroll
    for (int i = 0; i < ns; i++) {
        constexpr int CC = wtp::C / 2;
        const int l = la + i;
        op0[(l * l + l + m) * CC] = ACC[0][i];
        op1[(l * l + l + m) * CC] = ACC[1][i];
    }
}

// ============================================================================
// Hot kernel. Block = 128 threads = 8 ch-pairs x 16 row-slots; each thread
// owns 2 rows -> 16 channels x 32 rows per block. Grid = 512.
// launch_bounds(128,2): 256-reg cap gives ptxas room for the pipeline ring.
// ============================================================================
__global__ void __launch_bounds__(wtp::NTHREADS, 2)
wtp_kernel(const float* __restrict__ x1,
           const float* __restrict__ x2,
           float* __restrict__ out)
{
    extern __shared__ ull cgw_s[];  // [NNZ][NCHP], reference term order

    const int tid     = threadIdx.x;
    const int cgroup  = blockIdx.x & 7;
    const int rowbase = (blockIdx.x >> 3) * wtp::NROWB;
    const int cp      = tid & (wtp::NCHP - 1);
    const int rs      = tid >> 3;
    const int cbase   = cgroup * 16;

    // --- bulk copy global slice -> smem (1912 x 16B, fully coalesced) ---
    {
        const ulonglong2* src = reinterpret_cast<const ulonglong2*>(cgw_g[cgroup]);
        ulonglong2*       dst = reinterpret_cast<ulonglong2*>(cgw_s);
        #pragma unroll
        for (int i = tid; i < wtp::SLICE / 2; i += wtp::NTHREADS)
            dst[i] = src[i];
    }
    __syncthreads();

    const int row0 = rowbase + rs;
    const int row1 = row0 + wtp::NSLOT;
    const size_t base0 = (size_t)row0 * wtp::MOUT * wtp::C + cbase + cp * 2;
    const size_t base1 = (size_t)row1 * wtp::MOUT * wtp::C + cbase + cp * 2;
    const ull* x1p0 = reinterpret_cast<const ull*>(x1 + base0);
    const ull* x2p0 = reinterpret_cast<const ull*>(x2 + base0);
    const ull* x1p1 = reinterpret_cast<const ull*>(x1 + base1);
    const ull* x2p1 = reinterpret_cast<const ull*>(x2 + base1);
    ull* op0 = reinterpret_cast<ull*>(out + base0);
    ull* op1 = reinterpret_cast<ull*>(out + base1);

    ull X1[wtp::RPT][wtp::MOUT], X2[wtp::RPT][wtp::MOUT];
    #pragma unroll
    for (int m = 0; m < wtp::MOUT; m++) {
        constexpr int CC = wtp::C / 2;
        X1[0][m] = x1p0[m * CC];
        X2[0][m] = x2p0[m * CC];
        X1[1][m] = x1p1[m * CC];
        X2[1][m] = x2p1[m * CC];
    }

    const ull* cgw_tp = cgw_s + cp;

    // software-pipeline ring: preload first PIPE wv values
    ull wbuf[wtp::PIPE];
    pipe_prologue(std::make_integer_sequence<int, wtp::PIPE>{}, cgw_tp, wbuf);

    run_group<0>(cgw_tp, wbuf, X1, X2, op0, op1);
    run_group<1>(cgw_tp, wbuf, X1, X2, op0, op1);
    run_group<2>(cgw_tp, wbuf, X1, X2, op0, op1);
    run_group<3>(cgw_tp, wbuf, X1, X2, op0, op1);
    run_group<4>(cgw_tp, wbuf, X1, X2, op0, op1);
    run_group<5>(cgw_tp, wbuf, X1, X2, op0, op1);
    run_group<6>(cgw_tp, wbuf, X1, X2, op0, op1);
}

// ============================================================================
// Launch. Inputs (metadata order): x1, x2, weight, CG_vals, M1, M2, l_ind, M_seg
// ============================================================================
extern "C" void kernel_launch(void* const* d_in, const int* in_sizes, int n_in,
                              void* d_out, int out_size)
{
    const float* x1    = (const float*)d_in[0];
    const float* x2    = (const float*)d_in[1];
    const float* w     = (const float*)d_in[2];
    const float* cg    = (const float*)d_in[3];
    const int*   l_ind = (const int*)d_in[6];
    float*       out   = (float*)d_out;

    const int B = in_sizes[0] / (wtp::MOUT * wtp::C);   // 2048
    const int smem = wtp::SLICE * 8;                    // 30592 bytes

    cudaFuncSetAttribute(wtp_kernel, cudaFuncAttributeMaxDynamicSharedMemorySize, smem);

    // 1) build CG*weight table once
    wtp_build_kernel<<<120, 256>>>(w, cg, l_ind);

    // 2) hot kernel
    const int grid = (B / wtp::NROWB) * wtp::NCGRP;     // 64 * 8 = 512
    wtp_kernel<<<grid, wtp::NTHREADS, smem>>>(x1, x2, out);
}